// round 13
// baseline (speedup 1.0000x reference)
#include <cuda.h>
#include <cuda_runtime.h>
#include <cuda_bf16.h>

// GraphNorm, persistent TMA pipeline (sm_103a-native).
//   out = a*x + b,  a = gnw*rsqrt(var+eps), b = gnb - a*m*msc
//   var = E[x^2] - 2*(m*msc)*m + (m*msc)^2  (single sweep)
//
// Tile = (graph, 16-col chunk) = 512x16 fp32 = 32 KB. Ring of 3 SMEM buffers.
// Per tile: ONE elected thread issues a 2-box TMA load (mbarrier complete_tx)
// and, after in-place apply, a 2-box TMA store (bulk_group). Warps never touch
// global memory on the hot path. 256 thr/CTA, 2 CTAs/SM, 304 persistent CTAs.
//
// cuTensorMapEncodeTiled is resolved at runtime through cudart
// (cudaGetDriverEntryPointByVersion) because the harness does not link -lcuda.

#define TILE_D    16
#define THREADS   256
#define ROW_TILE  512
#define BOX_ROWS  256                     // TMA box dim limit
#define NWARPS    (THREADS / 32)          // 8
#define NBUF      3
#define BUF_ELEMS (ROW_TILE * TILE_D)     // 8192 floats = 32 KB
#define PS_ELEMS  (NWARPS * TILE_D)       // 128 floats
#define TPR       4                       // threads per row (float4)
#define ROWSTEP   (THREADS / TPR)         // 64 rows per pass
#define NPASS     (ROW_TILE / ROWSTEP)    // 8
#define TILE_BYTES (BUF_ELEMS * 4)        // 32768
#define EPSV      1e-6f
#define NCTA      304                     // 2 per SM x 152 SMs

#define SMEM_BYTES (NBUF*TILE_BYTES + 2*PS_ELEMS*4 + 64)

__device__ __forceinline__ unsigned smem_u32(const void* p) {
    return (unsigned)__cvta_generic_to_shared(p);
}
__device__ __forceinline__ void mbar_init(unsigned mbar, unsigned count) {
    asm volatile("mbarrier.init.shared.b64 [%0], %1;" :: "r"(mbar), "r"(count) : "memory");
}
__device__ __forceinline__ void mbar_expect_tx(unsigned mbar, unsigned bytes) {
    asm volatile("mbarrier.arrive.expect_tx.shared.b64 _, [%0], %1;"
                 :: "r"(mbar), "r"(bytes) : "memory");
}
__device__ __forceinline__ void mbar_wait(unsigned mbar, unsigned parity) {
    asm volatile(
        "{\n\t.reg .pred P;\n"
        "W_%=:\n\t"
        "mbarrier.try_wait.parity.acquire.cta.shared::cta.b64 P, [%0], %1, 0x989680;\n\t"
        "@P bra D_%=;\n\t"
        "bra W_%=;\n"
        "D_%=:\n\t}"
        :: "r"(mbar), "r"(parity) : "memory");
}
__device__ __forceinline__ void tma_load_2d(unsigned sdst, const CUtensorMap* tm,
                                            int cx, int cy, unsigned mbar) {
    asm volatile(
        "cp.async.bulk.tensor.2d.shared::cta.global.tile.mbarrier::complete_tx::bytes "
        "[%0], [%1, {%2, %3}], [%4];"
        :: "r"(sdst), "l"(tm), "r"(cx), "r"(cy), "r"(mbar) : "memory");
}
__device__ __forceinline__ void tma_store_2d(const CUtensorMap* tm,
                                             int cx, int cy, unsigned ssrc) {
    asm volatile(
        "cp.async.bulk.tensor.2d.global.shared::cta.tile.bulk_group "
        "[%0, {%1, %2}], [%3];"
        :: "l"(tm), "r"(cx), "r"(cy), "r"(ssrc) : "memory");
}
__device__ __forceinline__ void tma_commit() {
    asm volatile("cp.async.bulk.commit_group;" ::: "memory");
}
template <int N> __device__ __forceinline__ void tma_wait_group() {
    asm volatile("cp.async.bulk.wait_group %0;" :: "n"(N) : "memory");
}
__device__ __forceinline__ void fence_async() {
    asm volatile("fence.proxy.async.shared::cta;" ::: "memory");
}

__device__ __forceinline__ void acc4(float4 v, float4& s1, float4& s2) {
    s1.x += v.x; s1.y += v.y; s1.z += v.z; s1.w += v.w;
    s2.x = fmaf(v.x, v.x, s2.x);
    s2.y = fmaf(v.y, v.y, s2.y);
    s2.z = fmaf(v.z, v.z, s2.z);
    s2.w = fmaf(v.w, v.w, s2.w);
}

__global__ __launch_bounds__(THREADS, 2)
void graphnorm_tma_kernel(const __grid_constant__ CUtensorMap tmx,
                          const __grid_constant__ CUtensorMap tmo,
                          const float* __restrict__ x,
                          const float* __restrict__ gnw,
                          const float* __restrict__ gnb,
                          const float* __restrict__ msc,
                          const int* __restrict__ bn,
                          float* __restrict__ out,
                          int D, int B)
{
    extern __shared__ float smem[];
    float* ps1 = smem + NBUF * BUF_ELEMS;
    float* ps2 = ps1 + PS_ELEMS;
    unsigned long long* mb = (unsigned long long*)(ps2 + PS_ELEMS);

    const int tid  = threadIdx.x;
    const int wid  = tid >> 5;
    const int lane = tid & 31;
    const int ncc  = D / TILE_D;
    const int ntiles = B * ncc;

    const int l4   = (tid & (TPR - 1)) * 4;   // 0,4,8,12
    const int row0 = tid / TPR;               // 0..63

    const int t0 = blockIdx.x;
    const int stride = gridDim.x;
    if (t0 >= ntiles) return;

    if (tid == 0) {
        #pragma unroll
        for (int s = 0; s < NBUF; ++s) mbar_init(smem_u32(&mb[s]), 1);
    }
    __syncthreads();

    unsigned phases = 0;   // per-buffer parity bits

    // prefetch cursor / compute cursor
    int pgP = 0; long long startP = 0; int tP = t0;
    int pg = 0;  long long pstart = 0; int t = t0;

    // prologue: issue load of tile t0 into slot 0
    {
        const int g = tP / ncc;
        while (pgP < g) startP += (long long)bn[pgP++];
        const int cx = (tP % ncc) * TILE_D;
        const int cy = (int)startP;
        if (tid == 0) {
            unsigned m = smem_u32(&mb[0]);
            mbar_expect_tx(m, 2 * BOX_ROWS * TILE_D * 4);
            tma_load_2d(smem_u32(smem), &tmx, cx, cy, m);
            tma_load_2d(smem_u32(smem + BOX_ROWS * TILE_D), &tmx, cx, cy + BOX_ROWS, m);
        }
        tP += stride;
    }

    int i = 0;
    for (;;) {
        const int slot_c = i % NBUF;
        const int slot_n = (i + 1) % NBUF;

        // resolve + issue next tile's load (slot_n's old store, tile i-2,
        // is guaranteed drained by wait_group<1> before reuse)
        const bool has_next = (tP < ntiles);
        if (has_next) {
            const int gn = tP / ncc;
            while (pgP < gn) startP += (long long)bn[pgP++];
            const int cx = (tP % ncc) * TILE_D;
            const int cy = (int)startP;
            if (tid == 0) {
                tma_wait_group<1>();
                unsigned m = smem_u32(&mb[slot_n]);
                mbar_expect_tx(m, 2 * BOX_ROWS * TILE_D * 4);
                float* nb = smem + slot_n * BUF_ELEMS;
                tma_load_2d(smem_u32(nb), &tmx, cx, cy, m);
                tma_load_2d(smem_u32(nb + BOX_ROWS * TILE_D), &tmx, cx, cy + BOX_ROWS, m);
            }
            tP += stride;
        }

        // current tile metadata
        const int g = t / ncc;
        while (pg < g) pstart += (long long)bn[pg++];
        const int cnt = bn[g];
        const int cpn = min(cnt, ROW_TILE);
        const int cc  = t % ncc;
        float* cb = smem + slot_c * BUF_ELEMS;
        const float* cxg = x + pstart * (long long)D + cc * TILE_D;

        // wait for current tile's TMA load
        mbar_wait(smem_u32(&mb[slot_c]), (phases >> slot_c) & 1u);
        phases ^= 1u << slot_c;

        // ---- reduce (capture in registers) ----
        float4 v[NPASS];
        float4 s1 = make_float4(0.f, 0.f, 0.f, 0.f);
        float4 s2 = make_float4(0.f, 0.f, 0.f, 0.f);
        const bool full = (cnt == ROW_TILE);
        if (full) {
            const float* tp = cb + row0 * TILE_D + l4;
            #pragma unroll
            for (int it = 0; it < NPASS; ++it) {
                v[it] = *(const float4*)(tp + it * ROWSTEP * TILE_D);
                acc4(v[it], s1, s2);
            }
        } else {
            for (int r = row0; r < cpn; r += ROWSTEP)
                acc4(*(const float4*)(cb + r * TILE_D + l4), s1, s2);
            for (int r = ROW_TILE + row0; r < cnt; r += ROWSTEP)
                acc4(*(const float4*)(cxg + (long long)r * D + l4), s1, s2);
        }

        #pragma unroll
        for (int off = TPR; off < 32; off <<= 1) {
            s1.x += __shfl_xor_sync(0xffffffffu, s1.x, off);
            s1.y += __shfl_xor_sync(0xffffffffu, s1.y, off);
            s1.z += __shfl_xor_sync(0xffffffffu, s1.z, off);
            s1.w += __shfl_xor_sync(0xffffffffu, s1.w, off);
            s2.x += __shfl_xor_sync(0xffffffffu, s2.x, off);
            s2.y += __shfl_xor_sync(0xffffffffu, s2.y, off);
            s2.z += __shfl_xor_sync(0xffffffffu, s2.z, off);
            s2.w += __shfl_xor_sync(0xffffffffu, s2.w, off);
        }
        if (lane < TPR) {
            *(float4*)(ps1 + wid * TILE_D + lane * 4) = s1;
            *(float4*)(ps2 + wid * TILE_D + lane * 4) = s2;
        }
        __syncthreads();    // partials visible; all reduce LDS of cb complete

        // ---- warp-redundant coeffs, shfl broadcast ----
        float a = 0.f, b = 0.f;
        if (lane < TILE_D) {
            float t1 = 0.f, t2 = 0.f;
            #pragma unroll
            for (int k = 0; k < NWARPS; ++k) {
                t1 += ps1[k * TILE_D + lane];
                t2 += ps2[k * TILE_D + lane];
            }
            const float inv_n = 1.0f / (float)cnt;
            const float m    = t1 * inv_n;
            const float ex2  = t2 * inv_n;
            const float s    = msc[cc * TILE_D + lane];
            const float ms   = m * s;
            const float var  = ex2 - 2.f * ms * m + ms * ms;
            const float rstd = rsqrtf(var + EPSV);
            a = gnw[cc * TILE_D + lane] * rstd;
            b = gnb[cc * TILE_D + lane] - a * ms;
        }
        float4 av, bv;
        av.x = __shfl_sync(0xffffffffu, a, l4 + 0);
        av.y = __shfl_sync(0xffffffffu, a, l4 + 1);
        av.z = __shfl_sync(0xffffffffu, a, l4 + 2);
        av.w = __shfl_sync(0xffffffffu, a, l4 + 3);
        bv.x = __shfl_sync(0xffffffffu, b, l4 + 0);
        bv.y = __shfl_sync(0xffffffffu, b, l4 + 1);
        bv.z = __shfl_sync(0xffffffffu, b, l4 + 2);
        bv.w = __shfl_sync(0xffffffffu, b, l4 + 3);

        if (full) {
            // ---- apply in place (own slots only; values held in regs) ----
            float* tp = cb + row0 * TILE_D + l4;
            #pragma unroll
            for (int it = 0; it < NPASS; ++it) {
                float4 o;
                o.x = fmaf(av.x, v[it].x, bv.x);
                o.y = fmaf(av.y, v[it].y, bv.y);
                o.z = fmaf(av.z, v[it].z, bv.z);
                o.w = fmaf(av.w, v[it].w, bv.w);
                *(float4*)(tp + it * ROWSTEP * TILE_D) = o;
            }
            __syncthreads();    // all STS done before TMA reads SMEM
            if (tid == 0) {
                fence_async();
                const int cx = cc * TILE_D;
                const int cy = (int)pstart;
                tma_store_2d(&tmo, cx, cy, smem_u32(cb));
                tma_store_2d(&tmo, cx, cy + BOX_ROWS, smem_u32(cb + BOX_ROWS * TILE_D));
                tma_commit();
            }
        } else {
            // fallback: direct stores (keeps group accounting positional)
            float* og = out + pstart * (long long)D + cc * TILE_D;
            for (int r = row0; r < cpn; r += ROWSTEP) {
                float4 w = *(const float4*)(cb + r * TILE_D + l4);
                float4 o;
                o.x = fmaf(av.x, w.x, bv.x);
                o.y = fmaf(av.y, w.y, bv.y);
                o.z = fmaf(av.z, w.z, bv.z);
                o.w = fmaf(av.w, w.w, bv.w);
                __stcs((float4*)(og + (long long)r * D + l4), o);
            }
            for (int r = ROW_TILE + row0; r < cnt; r += ROWSTEP) {
                float4 w = *(const float4*)(cxg + (long long)r * D + l4);
                float4 o;
                o.x = fmaf(av.x, w.x, bv.x);
                o.y = fmaf(av.y, w.y, bv.y);
                o.z = fmaf(av.z, w.z, bv.z);
                o.w = fmaf(av.w, w.w, bv.w);
                __stcs((float4*)(og + (long long)r * D + l4), o);
            }
            __syncthreads();
            if (tid == 0) tma_commit();   // empty group
        }

        if (!has_next) break;
        t += stride;
        ++i;
    }
    if (tid == 0) tma_wait_group<0>();
}

// ---- host side: resolve cuTensorMapEncodeTiled through cudart ----
typedef CUresult (*PFN_encodeTiled)(
    CUtensorMap*, CUtensorMapDataType, cuuint32_t, void*,
    const cuuint64_t*, const cuuint64_t*, const cuuint32_t*, const cuuint32_t*,
    CUtensorMapInterleave, CUtensorMapSwizzle, CUtensorMapL2promotion,
    CUtensorMapFloatOOBfill);

static PFN_encodeTiled get_encode_fn()
{
    void* fn = nullptr;
    cudaDriverEntryPointQueryResult st;
#if CUDART_VERSION >= 12050
    cudaGetDriverEntryPointByVersion("cuTensorMapEncodeTiled", &fn, 12000,
                                     cudaEnableDefault, &st);
#else
    cudaGetDriverEntryPoint("cuTensorMapEncodeTiled", &fn,
                            cudaEnableDefault, &st);
#endif
    return (PFN_encodeTiled)fn;
}

extern "C" void kernel_launch(void* const* d_in, const int* in_sizes, int n_in,
                              void* d_out, int out_size)
{
    const float* x   = (const float*)d_in[0];
    const float* gnw = (const float*)d_in[1];
    const float* gnb = (const float*)d_in[2];
    const float* msc = (const float*)d_in[3];
    const int*   bn  = (const int*)d_in[4];
    float* out = (float*)d_out;

    const int D = in_sizes[1];                 // HIDDEN
    const int B = in_sizes[4];                 // NUM_GRAPHS
    const long long N = in_sizes[0] / D;       // total rows

    PFN_encodeTiled encode = get_encode_fn();

    CUtensorMap tmx, tmo;
    {
        cuuint64_t dims[2]    = {(cuuint64_t)D, (cuuint64_t)N};
        cuuint64_t strides[1] = {(cuuint64_t)D * sizeof(float)};
        cuuint32_t box[2]     = {TILE_D, BOX_ROWS};
        cuuint32_t es[2]      = {1, 1};
        encode(&tmx, CU_TENSOR_MAP_DATA_TYPE_FLOAT32, 2,
               (void*)x, dims, strides, box, es,
               CU_TENSOR_MAP_INTERLEAVE_NONE, CU_TENSOR_MAP_SWIZZLE_NONE,
               CU_TENSOR_MAP_L2_PROMOTION_L2_128B,
               CU_TENSOR_MAP_FLOAT_OOB_FILL_NONE);
        encode(&tmo, CU_TENSOR_MAP_DATA_TYPE_FLOAT32, 2,
               (void*)out, dims, strides, box, es,
               CU_TENSOR_MAP_INTERLEAVE_NONE, CU_TENSOR_MAP_SWIZZLE_NONE,
               CU_TENSOR_MAP_L2_PROMOTION_L2_128B,
               CU_TENSOR_MAP_FLOAT_OOB_FILL_NONE);
    }

    cudaFuncSetAttribute(graphnorm_tma_kernel,
                         cudaFuncAttributeMaxDynamicSharedMemorySize,
                         (int)SMEM_BYTES);

    int ntiles = B * (D / TILE_D);
    int grid = ntiles < NCTA ? ntiles : NCTA;
    graphnorm_tma_kernel<<<grid, THREADS, SMEM_BYTES>>>(tmx, tmo, x, gnw, gnb,
                                                        msc, bn, out, D, B);
}

// round 14
// speedup vs baseline: 1.0098x; 1.0098x over previous
#include <cuda.h>
#include <cuda_runtime.h>

// GraphNorm, 128B-granular TMA producer/consumer pipeline.
//   out = a*x + b,  a = gnw*rsqrt(var+eps), b = gnb - a*m*msc
//   var = E[x^2] - 2*(m*msc)*m + (m*msc)^2  (single sweep)
//
// Unit = (graph, 32-col chunk): 512x32 fp32 = 64 KB, processed as two
// 256-row HALF tiles (32 KB) on a ring of 3 SMEM slots.
//   producer (tid 0): wait empty[slot] -> TMA load half (128B rows)
//   consumers (8 warps): wait full[slot] -> reduce into REGISTERS -> arrive empty
// Unit values live in registers (16 float4/thread), so slots recycle right
// after reduce; apply/store runs from regs via 128B-coalesced st.global.cs.
// One __syncthreads per unit. 256 thr/CTA, 2 CTAs/SM, 304 persistent CTAs.

#define TILE_D    32
#define THREADS   256
#define HALF_ROWS 256
#define FULL_ROWS 512
#define NBUF      3
#define HALF_ELEMS (HALF_ROWS * TILE_D)   // 8192 floats = 32 KB
#define HALF_BYTES (HALF_ELEMS * 4)
#define NWARPS    (THREADS / 32)          // 8
#define ROWSTEP   (THREADS / 8)           // 32 rows per pass (8 thr/row)
#define NPASS_H   (HALF_ROWS / ROWSTEP)   // 8
#define PS_STRIDE (NWARPS * TILE_D)       // 256 floats
#define EPSV      1e-6f
#define NCTA      304                     // 2 per SM x 152 SMs

#define SMEM_BYTES ((NBUF*HALF_ELEMS + 4*PS_STRIDE) * 4 + 64)

__device__ __forceinline__ unsigned smem_u32(const void* p) {
    return (unsigned)__cvta_generic_to_shared(p);
}
__device__ __forceinline__ void mbar_init(unsigned mbar, unsigned count) {
    asm volatile("mbarrier.init.shared.b64 [%0], %1;" :: "r"(mbar), "r"(count) : "memory");
}
__device__ __forceinline__ void mbar_expect_tx(unsigned mbar, unsigned bytes) {
    asm volatile("mbarrier.arrive.expect_tx.shared.b64 _, [%0], %1;"
                 :: "r"(mbar), "r"(bytes) : "memory");
}
__device__ __forceinline__ void mbar_arrive(unsigned mbar) {
    asm volatile("mbarrier.arrive.shared.b64 _, [%0];" :: "r"(mbar) : "memory");
}
__device__ __forceinline__ void mbar_wait(unsigned mbar, unsigned parity) {
    asm volatile(
        "{\n\t.reg .pred P;\n"
        "W_%=:\n\t"
        "mbarrier.try_wait.parity.acquire.cta.shared::cta.b64 P, [%0], %1, 0x989680;\n\t"
        "@P bra D_%=;\n\t"
        "bra W_%=;\n"
        "D_%=:\n\t}"
        :: "r"(mbar), "r"(parity) : "memory");
}
__device__ __forceinline__ void tma_load_2d(unsigned sdst, const CUtensorMap* tm,
                                            int cx, int cy, unsigned mbar) {
    asm volatile(
        "cp.async.bulk.tensor.2d.shared::cta.global.tile.mbarrier::complete_tx::bytes "
        "[%0], [%1, {%2, %3}], [%4];"
        :: "r"(sdst), "l"(tm), "r"(cx), "r"(cy), "r"(mbar) : "memory");
}

__device__ __forceinline__ void acc4(float4 v, float4& s1, float4& s2) {
    s1.x += v.x; s1.y += v.y; s1.z += v.z; s1.w += v.w;
    s2.x = fmaf(v.x, v.x, s2.x);
    s2.y = fmaf(v.y, v.y, s2.y);
    s2.z = fmaf(v.z, v.z, s2.z);
    s2.w = fmaf(v.w, v.w, s2.w);
}

__global__ __launch_bounds__(THREADS, 2)
void graphnorm_kernel(const __grid_constant__ CUtensorMap tmx,
                      const float* __restrict__ x,
                      const float* __restrict__ gnw,
                      const float* __restrict__ gnb,
                      const float* __restrict__ msc,
                      const int* __restrict__ bn,
                      float* __restrict__ out,
                      int D, int B)
{
    extern __shared__ float smem[];
    float* ps_base = smem + NBUF * HALF_ELEMS;         // 4*PS_STRIDE floats
    unsigned long long* mb = (unsigned long long*)(ps_base + 4 * PS_STRIDE);
    // mb[0..2] = full, mb[3..5] = empty

    const int tid  = threadIdx.x;
    const int wid  = tid >> 5;
    const int lane = tid & 31;
    const int ncc  = D / TILE_D;
    const int nunits = B * ncc;

    const int colg    = tid & 7;        // column group within 32 cols
    const int col_off = colg * 4;
    const int row0    = tid >> 3;       // 0..31

    const int u0 = blockIdx.x;
    const int stride = gridDim.x;
    if (u0 >= nunits) return;

    if (tid == 0) {
        #pragma unroll
        for (int s = 0; s < NBUF; ++s) {
            mbar_init(smem_u32(&mb[s]), 1);          // full: 1 (expect_tx arrive)
            mbar_init(smem_u32(&mb[NBUF + s]), NWARPS); // empty: 8 warp arrivals
        }
    }
    __syncthreads();

    // producer state (tid 0 only)
    int pgP = 0; long long startP = 0;
    int uP = u0, hP = 0, jP = 0;
    unsigned ep = 0x7u;   // empty parity bits: start 1 -> first wait passes
    // consumer state
    int pg = 0; long long pstart = 0;
    int u = u0, jC = 0;
    unsigned fp = 0;      // full parity bits
    int psel = 0;

#define ISSUE_NEXT()                                                          \
    do {                                                                      \
        if (uP < nunits) {                                                    \
            const int gP = uP / ncc;                                          \
            while (pgP < gP) startP += (long long)bn[pgP++];                  \
            const int slotP = jP % NBUF;                                      \
            mbar_wait(smem_u32(&mb[NBUF + slotP]), (ep >> slotP) & 1u);       \
            ep ^= 1u << slotP;                                                \
            unsigned mful = smem_u32(&mb[slotP]);                             \
            mbar_expect_tx(mful, HALF_BYTES);                                 \
            tma_load_2d(smem_u32(smem + slotP * HALF_ELEMS), &tmx,            \
                        (uP % ncc) * TILE_D,                                  \
                        (int)startP + hP * HALF_ROWS, mful);                  \
            ++jP;                                                             \
            if (++hP == 2) { hP = 0; uP += stride; }                          \
        }                                                                     \
    } while (0)

    // prologue: 2 halves in flight
    if (tid == 0) { ISSUE_NEXT(); ISSUE_NEXT(); }

    for (;;) {
        const int g = u / ncc;
        while (pg < g) pstart += (long long)bn[pg++];
        const int cnt = bn[g];
        const int cc  = u % ncc;

        float4 v[2 * NPASS_H];
        float4 s1 = make_float4(0.f, 0.f, 0.f, 0.f);
        float4 s2 = make_float4(0.f, 0.f, 0.f, 0.f);
        const bool full_graph = (cnt >= FULL_ROWS);

        #pragma unroll
        for (int h = 0; h < 2; ++h) {
            if (tid == 0) ISSUE_NEXT();          // keep depth-2 in flight
            const int slot = jC % NBUF;
            mbar_wait(smem_u32(&mb[slot]), (fp >> slot) & 1u);
            fp ^= 1u << slot;

            const float* tp = smem + slot * HALF_ELEMS + row0 * TILE_D + col_off;
            if (full_graph) {
                #pragma unroll
                for (int it = 0; it < NPASS_H; ++it) {
                    v[h * NPASS_H + it] = *(const float4*)(tp + it * ROWSTEP * TILE_D);
                    acc4(v[h * NPASS_H + it], s1, s2);
                }
            } else {
                #pragma unroll
                for (int it = 0; it < NPASS_H; ++it) {
                    v[h * NPASS_H + it] = *(const float4*)(tp + it * ROWSTEP * TILE_D);
                    if (h * HALF_ROWS + row0 + it * ROWSTEP < cnt)
                        acc4(v[h * NPASS_H + it], s1, s2);
                }
            }
            if (lane == 0) mbar_arrive(smem_u32(&mb[NBUF + slot]));
            ++jC;
        }

        // overflow rows (cnt > 512) straight from gmem
        const float* cxg = x + pstart * (long long)D + cc * TILE_D;
        for (int r = FULL_ROWS + row0; r < cnt; r += ROWSTEP)
            acc4(*(const float4*)(cxg + (long long)r * D + col_off), s1, s2);

        // collapse 4 row-lanes per column group (offsets 8, 16)
        #pragma unroll
        for (int off = 8; off <= 16; off <<= 1) {
            s1.x += __shfl_xor_sync(0xffffffffu, s1.x, off);
            s1.y += __shfl_xor_sync(0xffffffffu, s1.y, off);
            s1.z += __shfl_xor_sync(0xffffffffu, s1.z, off);
            s1.w += __shfl_xor_sync(0xffffffffu, s1.w, off);
            s2.x += __shfl_xor_sync(0xffffffffu, s2.x, off);
            s2.y += __shfl_xor_sync(0xffffffffu, s2.y, off);
            s2.z += __shfl_xor_sync(0xffffffffu, s2.z, off);
            s2.w += __shfl_xor_sync(0xffffffffu, s2.w, off);
        }
        float* ps1 = ps_base + psel * 2 * PS_STRIDE;
        float* ps2 = ps1 + PS_STRIDE;
        if (lane < 8) {
            *(float4*)(ps1 + wid * TILE_D + lane * 4) = s1;
            *(float4*)(ps2 + wid * TILE_D + lane * 4) = s2;
        }
        __syncthreads();   // the only barrier per unit

        // warp-redundant coeffs (all 32 lanes = 32 columns)
        float t1 = 0.f, t2 = 0.f;
        #pragma unroll
        for (int k = 0; k < NWARPS; ++k) {
            t1 += ps1[k * TILE_D + lane];
            t2 += ps2[k * TILE_D + lane];
        }
        const float inv_n = 1.0f / (float)cnt;
        const float m    = t1 * inv_n;
        const float ex2  = t2 * inv_n;
        const float sc   = msc[cc * TILE_D + lane];
        const float ms   = m * sc;
        const float var  = ex2 - 2.f * ms * m + ms * ms;
        const float rstd = rsqrtf(var + EPSV);
        const float a    = gnw[cc * TILE_D + lane] * rstd;
        const float b    = gnb[cc * TILE_D + lane] - a * ms;

        float4 av, bv;
        av.x = __shfl_sync(0xffffffffu, a, col_off + 0);
        av.y = __shfl_sync(0xffffffffu, a, col_off + 1);
        av.z = __shfl_sync(0xffffffffu, a, col_off + 2);
        av.w = __shfl_sync(0xffffffffu, a, col_off + 3);
        bv.x = __shfl_sync(0xffffffffu, b, col_off + 0);
        bv.y = __shfl_sync(0xffffffffu, b, col_off + 1);
        bv.z = __shfl_sync(0xffffffffu, b, col_off + 2);
        bv.w = __shfl_sync(0xffffffffu, b, col_off + 3);

        // ---- apply from registers, 128B-coalesced streaming stores ----
        float* og = out + pstart * (long long)D + cc * TILE_D + col_off;
        const long long rs = (long long)ROWSTEP * D;
        if (full_graph) {
            #pragma unroll
            for (int h = 0; h < 2; ++h) {
                float* q = og + (long long)(h * HALF_ROWS + row0) * D;
                #pragma unroll
                for (int it = 0; it < NPASS_H; ++it) {
                    float4 w = v[h * NPASS_H + it];
                    float4 o;
                    o.x = fmaf(av.x, w.x, bv.x);
                    o.y = fmaf(av.y, w.y, bv.y);
                    o.z = fmaf(av.z, w.z, bv.z);
                    o.w = fmaf(av.w, w.w, bv.w);
                    __stcs((float4*)(q + it * rs), o);
                }
            }
            for (int r = FULL_ROWS + row0; r < cnt; r += ROWSTEP) {
                float4 w = *(const float4*)(cxg + (long long)r * D + col_off);
                float4 o;
                o.x = fmaf(av.x, w.x, bv.x);
                o.y = fmaf(av.y, w.y, bv.y);
                o.z = fmaf(av.z, w.z, bv.z);
                o.w = fmaf(av.w, w.w, bv.w);
                __stcs((float4*)(og + (long long)r * D), o);
            }
        } else {
            #pragma unroll
            for (int h = 0; h < 2; ++h) {
                #pragma unroll
                for (int it = 0; it < NPASS_H; ++it) {
                    const int r = h * HALF_ROWS + row0 + it * ROWSTEP;
                    if (r < cnt) {
                        float4 w = v[h * NPASS_H + it];
                        float4 o;
                        o.x = fmaf(av.x, w.x, bv.x);
                        o.y = fmaf(av.y, w.y, bv.y);
                        o.z = fmaf(av.z, w.z, bv.z);
                        o.w = fmaf(av.w, w.w, bv.w);
                        __stcs((float4*)(og + (long long)r * D), o);
                    }
                }
            }
        }

        u += stride;
        if (u >= nunits) break;
        psel ^= 1;
    }
#undef ISSUE_NEXT
}

// ---- host side: resolve cuTensorMapEncodeTiled through cudart ----
typedef CUresult (*PFN_encodeTiled)(
    CUtensorMap*, CUtensorMapDataType, cuuint32_t, void*,
    const cuuint64_t*, const cuuint64_t*, const cuuint32_t*, const cuuint32_t*,
    CUtensorMapInterleave, CUtensorMapSwizzle, CUtensorMapL2promotion,
    CUtensorMapFloatOOBfill);

static PFN_encodeTiled get_encode_fn()
{
    void* fn = nullptr;
    cudaDriverEntryPointQueryResult st;
#if CUDART_VERSION >= 12050
    cudaGetDriverEntryPointByVersion("cuTensorMapEncodeTiled", &fn, 12000,
                                     cudaEnableDefault, &st);
#else
    cudaGetDriverEntryPoint("cuTensorMapEncodeTiled", &fn,
                            cudaEnableDefault, &st);
#endif
    return (PFN_encodeTiled)fn;
}

extern "C" void kernel_launch(void* const* d_in, const int* in_sizes, int n_in,
                              void* d_out, int out_size)
{
    const float* x   = (const float*)d_in[0];
    const float* gnw = (const float*)d_in[1];
    const float* gnb = (const float*)d_in[2];
    const float* msc = (const float*)d_in[3];
    const int*   bn  = (const int*)d_in[4];
    float* out = (float*)d_out;

    const int D = in_sizes[1];                 // HIDDEN
    const int B = in_sizes[4];                 // NUM_GRAPHS
    const long long N = in_sizes[0] / D;       // total rows

    PFN_encodeTiled encode = get_encode_fn();

    CUtensorMap tmx;
    {
        cuuint64_t dims[2]    = {(cuuint64_t)D, (cuuint64_t)N};
        cuuint64_t strides[1] = {(cuuint64_t)D * sizeof(float)};
        cuuint32_t box[2]     = {TILE_D, HALF_ROWS};
        cuuint32_t es[2]      = {1, 1};
        encode(&tmx, CU_TENSOR_MAP_DATA_TYPE_FLOAT32, 2,
               (void*)x, dims, strides, box, es,
               CU_TENSOR_MAP_INTERLEAVE_NONE, CU_TENSOR_MAP_SWIZZLE_NONE,
               CU_TENSOR_MAP_L2_PROMOTION_L2_128B,
               CU_TENSOR_MAP_FLOAT_OOB_FILL_NONE);
    }

    cudaFuncSetAttribute(graphnorm_kernel,
                         cudaFuncAttributeMaxDynamicSharedMemorySize,
                         (int)SMEM_BYTES);

    int nunits = B * (D / TILE_D);
    int grid = nunits < NCTA ? nunits : NCTA;
    graphnorm_kernel<<<grid, THREADS, SMEM_BYTES>>>(tmx, x, gnw, gnb, msc, bn,
                                                    out, D, B);
}